// round 13
// baseline (speedup 1.0000x reference)
#include <cuda_runtime.h>
#include <cuda_bf16.h>
#include <cstdint>

#define EMB 32
#define NUM_RADIAL 16
#define Z_CAP 96
#define EPB 256
#define RPAD 36
#define AST 20
#define KP1 20
#define KP2 36
#define TBL_FLOATS (2 * Z_CAP * RPAD)     // 6912 floats = 27648 B

// dynamic smem byte offsets
#define OFF_T   0
#define OFF_A   27648                      // sArbf: 512 rows x AST halfs = 20480 B
#define OFF_B1  (OFF_A + 512 * AST * 2)    // 48128: 2x32xKP1 halfs = 2560 B
#define OFF_B2  (OFF_B1 + 2 * 32 * KP1 * 2)// 50688: 2x32xKP2 halfs = 4608 B
#define OFF_Z   (OFF_B2 + 2 * 32 * KP2 * 2)// 55296: 2x256 ints = 2048 B
#define SMEM_TOTAL (OFF_Z + 2 * EPB * 4)   // 57344 B

typedef unsigned int uint;

__constant__ __align__(16) float c_Wr[NUM_RADIAL * EMB];
__constant__ __align__(16) float c_W3[EMB * EMB];
__constant__ __align__(16) float c_br[EMB];

__device__ __align__(16) float g_pad[TBL_FLOATS];

__global__ void precompute_emb_kernel(const float* __restrict__ emb_table,
                                      const float* __restrict__ W_dense,
                                      const float* __restrict__ b_dense,
                                      int num_z)
{
    int z = blockIdx.x;
    int j = threadIdx.x;
    if (z >= Z_CAP || j >= EMB) return;

    float acc1 = 0.0f, acc2 = 0.0f;
    if (z < num_z) {
        acc1 = b_dense[j];
#pragma unroll
        for (int k = 0; k < EMB; ++k) {
            float e = emb_table[z * EMB + k];
            acc1 += e * W_dense[k * EMB + j];
            acc2 += e * W_dense[(EMB + k) * EMB + j];
        }
    }
    g_pad[z * RPAD + j] = acc1;
    g_pad[Z_CAP * RPAD + z * RPAD + j] = acc2;
    if (j < RPAD - EMB) {
        g_pad[z * RPAD + EMB + j] = 0.0f;
        g_pad[Z_CAP * RPAD + z * RPAD + EMB + j] = 0.0f;
    }
}

// ---- helpers (validated in R8/R11) ----
__device__ __forceinline__ uint bf16pair(float lo, float hi) {
    uint r; asm("cvt.rn.bf16x2.f32 %0, %1, %2;" : "=r"(r) : "f"(hi), "f"(lo)); return r;
}
__device__ __forceinline__ void split2(float a, float b, uint& h, uint& l) {
    h = bf16pair(a, b);
    float ha = __uint_as_float(h << 16);
    float hb = __uint_as_float(h & 0xffff0000u);
    l = bf16pair(a - ha, b - hb);
}
__device__ __forceinline__ unsigned short bf16_1(float x) {
    return __bfloat16_as_ushort(__float2bfloat16(x));
}
__device__ __forceinline__ void mma16816(float* d, const uint* a, const uint* b) {
    asm("mma.sync.aligned.m16n8k16.row.col.f32.bf16.bf16.f32 "
        "{%0,%1,%2,%3}, {%4,%5,%6,%7}, {%8,%9}, {%0,%1,%2,%3};"
        : "+f"(d[0]), "+f"(d[1]), "+f"(d[2]), "+f"(d[3])
        : "r"(a[0]), "r"(a[1]), "r"(a[2]), "r"(a[3]), "r"(b[0]), "r"(b[1]));
}
__device__ __forceinline__ float silu_f(float s) {
    float th;
    asm("tanh.approx.f32 %0, %1;" : "=f"(th) : "f"(0.5f * s));
    return s * fmaf(0.5f, th, 0.5f);
}

__global__ __launch_bounds__(EPB, 2)
void dimenet_edge_kernel(const float* __restrict__ d_ij,
                         const float* __restrict__ frequencies,
                         const int*   __restrict__ Z,
                         const int*   __restrict__ idnb_i,
                         const int*   __restrict__ idnb_j,
                         float* __restrict__ out,
                         int E, int N)
{
    extern __shared__ __align__(16) char smem_raw[];
    float* sT = reinterpret_cast<float*>(smem_raw + OFF_T);
    unsigned short* sArbf = reinterpret_cast<unsigned short*>(smem_raw + OFF_A);
    unsigned short* sB1   = reinterpret_cast<unsigned short*>(smem_raw + OFF_B1);
    unsigned short* sB2   = reinterpret_cast<unsigned short*>(smem_raw + OFF_B2);
    int* sZi = reinterpret_cast<int*>(smem_raw + OFF_Z);
    int* sZj = sZi + EPB;

    const int tid = threadIdx.x;
    const int e   = blockIdx.x * EPB + tid;
    const int es  = (e < E) ? e : (E - 1);

    // ---- table copy gmem -> smem (coalesced; amortized over 256 edges) ----
    {
        const float4* src = reinterpret_cast<const float4*>(g_pad);
        float4* dst = reinterpret_cast<float4*>(sT);
        const int n4 = TBL_FLOATS / 4;                 // 1728
#pragma unroll
        for (int i = 0; i < (n4 + EPB - 1) / EPB; ++i) {
            int idx = i * EPB + tid;
            if (idx < n4) dst[idx] = __ldg(&src[idx]);
        }
    }

    // ---- bf16-split B matrices, transposed [n][k] (R8-validated layout) ----
#pragma unroll
    for (int i = 0; i < 2; ++i) {                      // 512 entries of W_rbf
        int idx = i * EPB + tid;
        int k = idx >> 5, n = idx & 31;
        float w = c_Wr[idx];
        unsigned short h = bf16_1(w);
        float hw = __uint_as_float((uint)h << 16);
        sB1[n * KP1 + k] = h;
        sB1[(32 + n) * KP1 + k] = bf16_1(w - hw);
    }
#pragma unroll
    for (int i = 0; i < 4; ++i) {                      // 1024 entries of W3
        int idx = i * EPB + tid;
        int k = idx >> 5, n = idx & 31;
        float w = c_W3[idx];
        unsigned short h = bf16_1(w);
        float hw = __uint_as_float((uint)h << 16);
        sB2[n * KP2 + k] = h;
        sB2[(32 + n) * KP2 + k] = bf16_1(w - hw);
    }

    // ---- per-edge z indices ----
    {
        int ni = idnb_i[es], nj = idnb_j[es];
        ni = min(max(ni, 0), N - 1);  nj = min(max(nj, 0), N - 1);
        int zi = Z[ni], zj = Z[nj];
        sZi[tid] = min(max(zi, 0), Z_CAP - 1);
        sZj[tid] = min(max(zj, 0), Z_CAP - 1);
    }

    // ---- rbf basis + bf16 split + staging (hi rows 0..255, lo rows 256..511) ----
    {
        const float d = d_ij[es];
        const float f0 = frequencies[0];
        const float x = d * 0.2f;
        const float x2 = x * x;
        const float x4 = x2 * x2;
        const float x5 = x4 * x;
        float env = 1.0f / x + x5 * (-28.0f + x * (48.0f - 21.0f * x));
        env = (x < 1.0f) ? env : 0.0f;

        float s, c0;
        sincosf(f0 * x, &s, &c0);
        const float twoc = 2.0f * c0;

        float rbf[NUM_RADIAL];
        float sm1 = 0.0f, sk = s;
#pragma unroll
        for (int k = 0; k < NUM_RADIAL; ++k) {
            rbf[k] = env * sk;
            float sp1 = twoc * sk - sm1;
            sm1 = sk; sk = sp1;
        }
#pragma unroll
        for (int c4 = 0; c4 < 4; ++c4) {
            uint h0, l0, h1, l1;
            split2(rbf[4*c4 + 0], rbf[4*c4 + 1], h0, l0);
            split2(rbf[4*c4 + 2], rbf[4*c4 + 3], h1, l1);
            *reinterpret_cast<uint2*>(&sArbf[tid * AST + c4 * 4])         = make_uint2(h0, h1);
            *reinterpret_cast<uint2*>(&sArbf[(EPB + tid) * AST + c4 * 4]) = make_uint2(l0, l1);
        }
    }
    __syncthreads();

    const int lane = tid & 31;
    const int warp = tid >> 5;                   // 0..7
    const int g  = lane >> 2;
    const int tg = lane & 3;
    const int rbase = warp * 32;

    // ---- GEMM1: u = rbf @ W_rbf + b_rbf  (M=32/warp, N=32, K=16) ----
    uint A1h[2][4], A1l[2][4];
#pragma unroll
    for (int mt = 0; mt < 2; ++mt) {
        int r = rbase + mt * 16 + g;
        A1h[mt][0] = *reinterpret_cast<const uint*>(&sArbf[r * AST + tg * 2]);
        A1h[mt][1] = *reinterpret_cast<const uint*>(&sArbf[(r + 8) * AST + tg * 2]);
        A1h[mt][2] = *reinterpret_cast<const uint*>(&sArbf[r * AST + tg * 2 + 8]);
        A1h[mt][3] = *reinterpret_cast<const uint*>(&sArbf[(r + 8) * AST + tg * 2 + 8]);
        int rl = EPB + r;
        A1l[mt][0] = *reinterpret_cast<const uint*>(&sArbf[rl * AST + tg * 2]);
        A1l[mt][1] = *reinterpret_cast<const uint*>(&sArbf[(rl + 8) * AST + tg * 2]);
        A1l[mt][2] = *reinterpret_cast<const uint*>(&sArbf[rl * AST + tg * 2 + 8]);
        A1l[mt][3] = *reinterpret_cast<const uint*>(&sArbf[(rl + 8) * AST + tg * 2 + 8]);
    }
    float acc1[2][4][4];
#pragma unroll
    for (int nt = 0; nt < 4; ++nt) {
        int n = nt * 8 + g;
        uint bh[2], bl[2];
        bh[0] = *reinterpret_cast<const uint*>(&sB1[n * KP1 + tg * 2]);
        bh[1] = *reinterpret_cast<const uint*>(&sB1[n * KP1 + tg * 2 + 8]);
        bl[0] = *reinterpret_cast<const uint*>(&sB1[(32 + n) * KP1 + tg * 2]);
        bl[1] = *reinterpret_cast<const uint*>(&sB1[(32 + n) * KP1 + tg * 2 + 8]);
        float2 bb = *reinterpret_cast<const float2*>(&c_br[nt * 8 + tg * 2]);
#pragma unroll
        for (int mt = 0; mt < 2; ++mt) {
            acc1[mt][nt][0] = bb.x; acc1[mt][nt][1] = bb.y;
            acc1[mt][nt][2] = bb.x; acc1[mt][nt][3] = bb.y;
            mma16816(acc1[mt][nt], A1h[mt], bh);
            mma16816(acc1[mt][nt], A1h[mt], bl);
            mma16816(acc1[mt][nt], A1l[mt], bh);
        }
    }

    // ---- silu(u) -> t, convert to GEMM2 A fragments in registers (R8-validated) ----
#pragma unroll
    for (int mt = 0; mt < 2; ++mt)
#pragma unroll
        for (int nt = 0; nt < 4; ++nt)
#pragma unroll
            for (int q = 0; q < 4; ++q)
                acc1[mt][nt][q] = silu_f(acc1[mt][nt][q]);

    uint A2h[2][2][4], A2l[2][2][4];
#pragma unroll
    for (int mt = 0; mt < 2; ++mt)
#pragma unroll
        for (int kt = 0; kt < 2; ++kt) {
            split2(acc1[mt][2*kt][0],   acc1[mt][2*kt][1],   A2h[mt][kt][0], A2l[mt][kt][0]);
            split2(acc1[mt][2*kt][2],   acc1[mt][2*kt][3],   A2h[mt][kt][1], A2l[mt][kt][1]);
            split2(acc1[mt][2*kt+1][0], acc1[mt][2*kt+1][1], A2h[mt][kt][2], A2l[mt][kt][2]);
            split2(acc1[mt][2*kt+1][2], acc1[mt][2*kt+1][3], A2h[mt][kt][3], A2l[mt][kt][3]);
        }

    // ---- GEMM2 accumulator init: emb1[zi] + emb2[zj] in fragment layout ----
    float acc2[2][4][4];
#pragma unroll
    for (int mt = 0; mt < 2; ++mt)
#pragma unroll
        for (int nt = 0; nt < 4; ++nt) {
            int r1 = rbase + mt * 16 + g, r2 = r1 + 8;
            int c = nt * 8 + tg * 2;
            float2 p1 = *reinterpret_cast<const float2*>(&sT[sZi[r1] * RPAD + c]);
            float2 q1 = *reinterpret_cast<const float2*>(&sT[Z_CAP * RPAD + sZj[r1] * RPAD + c]);
            float2 p2 = *reinterpret_cast<const float2*>(&sT[sZi[r2] * RPAD + c]);
            float2 q2 = *reinterpret_cast<const float2*>(&sT[Z_CAP * RPAD + sZj[r2] * RPAD + c]);
            acc2[mt][nt][0] = p1.x + q1.x;
            acc2[mt][nt][1] = p1.y + q1.y;
            acc2[mt][nt][2] = p2.x + q2.x;
            acc2[mt][nt][3] = p2.y + q2.y;
        }

    // ---- GEMM2: acc2 += t @ W3  (K=32, 3-term bf16 split) ----
#pragma unroll
    for (int kt = 0; kt < 2; ++kt) {
#pragma unroll
        for (int nt = 0; nt < 4; ++nt) {
            int n = nt * 8 + g;
            uint bh[2], bl[2];
            bh[0] = *reinterpret_cast<const uint*>(&sB2[n * KP2 + kt * 16 + tg * 2]);
            bh[1] = *reinterpret_cast<const uint*>(&sB2[n * KP2 + kt * 16 + tg * 2 + 8]);
            bl[0] = *reinterpret_cast<const uint*>(&sB2[(32 + n) * KP2 + kt * 16 + tg * 2]);
            bl[1] = *reinterpret_cast<const uint*>(&sB2[(32 + n) * KP2 + kt * 16 + tg * 2 + 8]);
#pragma unroll
            for (int mt = 0; mt < 2; ++mt) {
                mma16816(acc2[mt][nt], A2h[mt][kt], bh);
                mma16816(acc2[mt][nt], A2h[mt][kt], bl);
                mma16816(acc2[mt][nt], A2l[mt][kt], bh);
            }
        }
    }

    __syncthreads();   // all table reads done; reuse sT as SO staging

    // ---- two half-waves: warps [4w,4w+4) stage their 128 edges, all store ----
    float4* out4 = reinterpret_cast<float4*>(out);
    const long long base4 = (long long)blockIdx.x * (EPB * (EMB / 4));
#pragma unroll
    for (int w = 0; w < 2; ++w) {
        if ((warp >> 2) == w) {
            int lrbase = (warp & 3) * 32;
#pragma unroll
            for (int mt = 0; mt < 2; ++mt)
#pragma unroll
                for (int nt = 0; nt < 4; ++nt) {
                    int r1 = lrbase + mt * 16 + g, r2 = r1 + 8;
                    int c = nt * 8 + tg * 2;
                    float2 v1, v2;
                    v1.x = silu_f(acc2[mt][nt][0]); v1.y = silu_f(acc2[mt][nt][1]);
                    v2.x = silu_f(acc2[mt][nt][2]); v2.y = silu_f(acc2[mt][nt][3]);
                    *reinterpret_cast<float2*>(&sT[r1 * RPAD + c]) = v1;
                    *reinterpret_cast<float2*>(&sT[r2 * RPAD + c]) = v2;
                }
        }
        __syncthreads();
#pragma unroll
        for (int i = 0; i < 4; ++i) {
            int fidx = i * EPB + tid;            // 0..1023
            int el = fidx >> 3;
            int c  = fidx & 7;
            float4 v = *reinterpret_cast<const float4*>(&sT[el * RPAD + c * 4]);
            int eg = blockIdx.x * EPB + w * 128 + el;
            if (eg < E) out4[base4 + w * 1024 + fidx] = v;
        }
        __syncthreads();
    }
}

extern "C" void kernel_launch(void* const* d_in, const int* in_sizes, int n_in,
                              void* d_out, int out_size)
{
    const float* d_dij   = (const float*)d_in[0];
    const float* d_freq  = (const float*)d_in[1];
    const float* d_emb   = (const float*)d_in[2];
    const float* d_Wrbf  = (const float*)d_in[3];
    const float* d_brbf  = (const float*)d_in[4];
    const float* d_Wd    = (const float*)d_in[5];
    const float* d_bd    = (const float*)d_in[6];
    const int*   d_Z     = (const int*)d_in[7];
    const int*   d_i     = (const int*)d_in[8];
    const int*   d_j     = (const int*)d_in[9];
    float*       out     = (float*)d_out;

    const int E = in_sizes[0];
    const int N = in_sizes[7];
    int num_z   = in_sizes[2] / EMB;
    if (num_z > Z_CAP) num_z = Z_CAP;
    if (num_z < 1)     num_z = 1;

    cudaFuncSetAttribute(dimenet_edge_kernel,
                         cudaFuncAttributeMaxDynamicSharedMemorySize, SMEM_TOTAL);

    cudaMemcpyToSymbolAsync(c_Wr, d_Wrbf, NUM_RADIAL * EMB * sizeof(float), 0,
                            cudaMemcpyDeviceToDevice);
    cudaMemcpyToSymbolAsync(c_W3, d_Wd + (size_t)(2 * EMB) * EMB,
                            EMB * EMB * sizeof(float), 0,
                            cudaMemcpyDeviceToDevice);
    cudaMemcpyToSymbolAsync(c_br, d_brbf, EMB * sizeof(float), 0,
                            cudaMemcpyDeviceToDevice);

    precompute_emb_kernel<<<Z_CAP, EMB>>>(d_emb, d_Wd, d_bd, num_z);

    const int blocks = (E + EPB - 1) / EPB;
    dimenet_edge_kernel<<<blocks, EPB, SMEM_TOTAL>>>(d_dij, d_freq, d_Z, d_i, d_j, out, E, N);
}